// round 7
// baseline (speedup 1.0000x reference)
#include <cuda_runtime.h>

// PostProcessingBlock: 50 NOTEARS-style iterations, 512 independent 64x64
// matrices, one 256-thread CTA per matrix, 3 CTAs/SM.
// 8 matmuls/iter (algebraic minimum for m^63 + free trace(m^30) via m^15 dot).
// All chains alias-free via 3 rotating work buffers (no in-place squaring).
// f32x2 packed FMA, 2x8 tile per thread (1 dup-MOV feeds 4 FFMA2).

#define LDM   68
#define MATF  (64 * LDM)
#define NTH   256

typedef unsigned long long u64;

__device__ __forceinline__ u64 rep2(float v) {
    u64 r;
    asm("mov.b64 %0, {%1, %1};" : "=l"(r) : "r"(__float_as_uint(v)));
    return r;
}
__device__ __forceinline__ void ffma2(u64& d, u64 a, u64 b) {
    asm("fma.rn.f32x2 %0, %1, %2, %0;" : "+l"(d) : "l"(a), "l"(b));
}

// C = A @ B, 64x64x64 fp32 in smem, 256 threads, 2x8 tile per thread.
// No aliasing between C and A/B (caller guarantees distinct buffers;
// A == B is fine, operands are read-only).
__device__ __forceinline__ void mm64(float* __restrict__ C,
                                     const float* __restrict__ A,
                                     const float* __restrict__ B,
                                     int tx, int ty)
{
    u64 acc[2][4];
#pragma unroll
    for (int c = 0; c < 4; c++) { acc[0][c] = 0ULL; acc[1][c] = 0ULL; }

    const float* bcol = B + tx;

#pragma unroll 4
    for (int k0 = 0; k0 < 64; k0 += 4) {
        float a0[4], a1[4];
        *reinterpret_cast<float4*>(a0) = *reinterpret_cast<const float4*>(A + (ty + 0) * LDM + k0);
        *reinterpret_cast<float4*>(a1) = *reinterpret_cast<const float4*>(A + (ty + 1) * LDM + k0);

#pragma unroll
        for (int ki = 0; ki < 4; ki++) {
            const float* bp = bcol + (k0 + ki) * LDM;
            const ulonglong2 bl = *reinterpret_cast<const ulonglong2*>(bp);
            const ulonglong2 bh = *reinterpret_cast<const ulonglong2*>(bp + 4);
            const u64 d0 = rep2(a0[ki]);
            const u64 d1 = rep2(a1[ki]);
            ffma2(acc[0][0], d0, bl.x); ffma2(acc[0][1], d0, bl.y);
            ffma2(acc[0][2], d0, bh.x); ffma2(acc[0][3], d0, bh.y);
            ffma2(acc[1][0], d1, bl.x); ffma2(acc[1][1], d1, bl.y);
            ffma2(acc[1][2], d1, bh.x); ffma2(acc[1][3], d1, bh.y);
        }
    }

    float* c0 = C + (ty + 0) * LDM + tx;
    float* c1 = C + (ty + 1) * LDM + tx;
    *reinterpret_cast<ulonglong2*>(c0)     = make_ulonglong2(acc[0][0], acc[0][1]);
    *reinterpret_cast<ulonglong2*>(c0 + 4) = make_ulonglong2(acc[0][2], acc[0][3]);
    *reinterpret_cast<ulonglong2*>(c1)     = make_ulonglong2(acc[1][0], acc[1][1]);
    *reinterpret_cast<ulonglong2*>(c1 + 4) = make_ulonglong2(acc[1][2], acc[1][3]);
}

__global__ __launch_bounds__(NTH, 3)
void ppb_kernel(const float* __restrict__ adj, float* __restrict__ out)
{
    extern __shared__ float sm[];
    float* xs = sm;                 // current x
    float* w0 = xs + MATF;          // rotating work buffers
    float* w1 = w0 + MATF;
    float* w2 = w1 + MATF;
    float* red = w2 + MATF;         // [0..7] warp partials, [8] alpha

    const int tid = threadIdx.x;
    const int tx = (tid & 7) * 8;      // 8 output columns
    const int ty = (tid >> 3) * 2;     // 2 output rows
    const int bidx = blockIdx.x;
    const float4* Ain4 = reinterpret_cast<const float4*>(adj + (size_t)bidx * 4096);

    // Load adj -> xs; scores = threshold(adj,0.5) kept in 16 registers.
    float scf[16];
#pragma unroll
    for (int s = 0; s < 4; s++) {
        const int e4 = tid + s * NTH;
        const float4 v = Ain4[e4];
        const int i = e4 >> 4, j = (e4 & 15) * 4;
        float* xp = xs + i * LDM + j;
        xp[0] = v.x; xp[1] = v.y; xp[2] = v.z; xp[3] = v.w;
        scf[s * 4 + 0] = (v.x > 0.5f) ? v.x : 0.0f;
        scf[s * 4 + 1] = (v.y > 0.5f) ? v.y : 0.0f;
        scf[s * 4 + 2] = (v.z > 0.5f) ? v.z : 0.0f;
        scf[s * 4 + 3] = (v.w > 0.5f) ? v.w : 0.0f;
    }
    if (tid == 0) red[8] = 0.0f;
    __syncthreads();

    const float INV64  = 1.0f / 64.0f;
    const float SHRINK = 0.002f * 0.01f;

    // Invariant at loop top (iter >= 1): pA = m^15(x), pB = m^3(x), pC free.
    float* pA = w0;
    float* pB = w1;
    float* pC = w2;

#pragma unroll 1
    for (int it = 0; it < 50; it++) {
        const float alpha = red[8];
        const bool need_poly = (alpha != 0.0f);   // iter 0 only

        if (need_poly) {
            // m^63 = ((m^15)^2)^2 @ m^3 — all destinations distinct from sources.
            mm64(pC, pA, pA, tx, ty);  __syncthreads();  // m^30 -> pC (m^15 dead)
            mm64(pA, pC, pC, tx, ty);  __syncthreads();  // m^60 -> pA
            mm64(pC, pA, pB, tx, ty);  __syncthreads();  // m^63 -> pC (m^30 dead)
        }

        // x update (reads pC^T) fused with build of m = I + x*x/64 into pA.
        const float a2s = 2.0f * alpha * INV64;
#pragma unroll
        for (int s = 0; s < 4; s++) {
            const int e4 = tid + s * NTH;
            const int i = e4 >> 4, j = (e4 & 15) * 4;
            float* xp = xs + i * LDM + j;
            float* mp = pA + i * LDM + j;
#pragma unroll
            for (int c = 0; c < 4; c++) {
                float x = xp[c];
                float g = -scf[s * 4 + c];
                if (need_poly)
                    g += (a2s * x) * pC[(j + c) * LDM + i];
                const float til = x - 0.01f * g;
                float nx = fabsf(til) - SHRINK;
                nx = fmaxf(nx, 0.0f);
                x = 1.0f - fmaxf(1.0f - nx, 0.0f);
                xp[c] = x;
                mp[c] = x * x * INV64 + ((i == j + c) ? 1.0f : 0.0f);
            }
        }
        __syncthreads();

        // trace chain: m (pA) -> m^2, m^3, m^6, m^12, m^15; keep m^15 & m^3.
        mm64(pB, pA, pA, tx, ty);  __syncthreads();  // m^2  -> pB (m^3_old dead)
        mm64(pC, pB, pA, tx, ty);  __syncthreads();  // m^3  -> pC (m^63 dead)
        mm64(pB, pC, pC, tx, ty);  __syncthreads();  // m^6  -> pB (m^2 dead)
        mm64(pA, pB, pB, tx, ty);  __syncthreads();  // m^12 -> pA (m dead)
        mm64(pB, pA, pC, tx, ty);  __syncthreads();  // m^15 -> pB (m^6 dead)

        // h = trace(m^30)/64 - 1 ; trace(m^30) = dot(m^15, m^15^T)
        float part = 0.0f;
#pragma unroll
        for (int s = 0; s < 16; s++) {
            const int e = tid + s * NTH;
            const int i = e >> 6, k = e & 63;
            part += pB[i * LDM + k] * pB[k * LDM + i];
        }
#pragma unroll
        for (int off = 16; off > 0; off >>= 1)
            part += __shfl_xor_sync(0xFFFFFFFFu, part, off);
        if ((tid & 31) == 0) red[tid >> 5] = part;
        __syncthreads();
        if (tid == 0) {
            float t = 0.0f;
#pragma unroll
            for (int w = 0; w < 8; w++) t += red[w];
            red[8] += 0.01f * (t * INV64 - 1.0f);
        }

        // rotate: m^15 in pB, m^3 in pC, pA free.
        float* tmp = pA;
        pA = pB;      // m^15
        pB = pC;      // m^3
        pC = tmp;     // free
        __syncthreads();
    }

    // output = threshold(x, 0.5)
    float4* Out4 = reinterpret_cast<float4*>(out + (size_t)bidx * 4096);
#pragma unroll
    for (int s = 0; s < 4; s++) {
        const int e4 = tid + s * NTH;
        const int i = e4 >> 4, j = (e4 & 15) * 4;
        const float* xp = xs + i * LDM + j;
        float4 v;
        v.x = (xp[0] > 0.5f) ? xp[0] : 0.0f;
        v.y = (xp[1] > 0.5f) ? xp[1] : 0.0f;
        v.z = (xp[2] > 0.5f) ? xp[2] : 0.0f;
        v.w = (xp[3] > 0.5f) ? xp[3] : 0.0f;
        Out4[e4] = v;
    }
}

extern "C" void kernel_launch(void* const* d_in, const int* in_sizes, int n_in,
                              void* d_out, int out_size)
{
    const float* adj = (const float*)d_in[0];
    float* out = (float*)d_out;

    const int batches = in_sizes[0] >> 12;
    const size_t smem = (size_t)(4 * MATF + 16) * sizeof(float);

    cudaFuncSetAttribute(ppb_kernel, cudaFuncAttributeMaxDynamicSharedMemorySize, (int)smem);
    ppb_kernel<<<batches, NTH, smem>>>(adj, out);
}

// round 8
// speedup vs baseline: 2.4801x; 2.4801x over previous
#include <cuda_runtime.h>

// PostProcessingBlock: 50 NOTEARS-style iterations, 512 independent 64x64
// matrices, one 256-thread CTA per matrix, 3 CTAs/SM.
// 8 matmuls/iter: poly m^63 = ((m^15)^2)^2 @ m^3 reuses the previous trace
// chain's m^15/m^3 (x unchanged in between); trace(m^30) = dot(m^15, m^15^T).
// mm64: f32x2 packed FMA, 4x4 tile per thread (R6-proven shape).
// Chains are alias-free via 3 rotating buffers (no in-place squaring).

#define LDM   68
#define MATF  (64 * LDM)
#define NTH   256

typedef unsigned long long u64;

__device__ __forceinline__ u64 rep2(float v) {
    u64 r;
    asm("mov.b64 %0, {%1, %1};" : "=l"(r) : "r"(__float_as_uint(v)));
    return r;
}
__device__ __forceinline__ void ffma2(u64& d, u64 a, u64 b) {
    asm("fma.rn.f32x2 %0, %1, %2, %0;" : "+l"(d) : "l"(a), "l"(b));
}

// C = A @ B, 64x64x64 fp32 in smem, 256 threads, 4x4 tile per thread.
// Caller guarantees C is a distinct buffer from A and B (A == B allowed).
__device__ __forceinline__ void mm64(float* __restrict__ C,
                                     const float* __restrict__ A,
                                     const float* __restrict__ B,
                                     int tx, int ty)
{
    u64 acc[4][2];
#pragma unroll
    for (int r = 0; r < 4; r++) { acc[r][0] = 0ULL; acc[r][1] = 0ULL; }

#pragma unroll 4
    for (int k0 = 0; k0 < 64; k0 += 4) {
        float a0[4], a1[4], a2[4], a3[4];
        *reinterpret_cast<float4*>(a0) = *reinterpret_cast<const float4*>(A + (ty + 0) * LDM + k0);
        *reinterpret_cast<float4*>(a1) = *reinterpret_cast<const float4*>(A + (ty + 1) * LDM + k0);
        *reinterpret_cast<float4*>(a2) = *reinterpret_cast<const float4*>(A + (ty + 2) * LDM + k0);
        *reinterpret_cast<float4*>(a3) = *reinterpret_cast<const float4*>(A + (ty + 3) * LDM + k0);

#pragma unroll
        for (int ki = 0; ki < 4; ki++) {
            const ulonglong2 b = *reinterpret_cast<const ulonglong2*>(B + (k0 + ki) * LDM + tx);
            ffma2(acc[0][0], rep2(a0[ki]), b.x);
            ffma2(acc[0][1], rep2(a0[ki]), b.y);
            ffma2(acc[1][0], rep2(a1[ki]), b.x);
            ffma2(acc[1][1], rep2(a1[ki]), b.y);
            ffma2(acc[2][0], rep2(a2[ki]), b.x);
            ffma2(acc[2][1], rep2(a2[ki]), b.y);
            ffma2(acc[3][0], rep2(a3[ki]), b.x);
            ffma2(acc[3][1], rep2(a3[ki]), b.y);
        }
    }

#pragma unroll
    for (int r = 0; r < 4; r++)
        *reinterpret_cast<ulonglong2*>(C + (ty + r) * LDM + tx) =
            make_ulonglong2(acc[r][0], acc[r][1]);
}

__global__ __launch_bounds__(NTH, 3)
void ppb_kernel(const float* __restrict__ adj, float* __restrict__ out)
{
    extern __shared__ float sm[];
    float* xs = sm;                 // current x
    float* w0 = xs + MATF;          // rotating work buffers
    float* w1 = w0 + MATF;
    float* w2 = w1 + MATF;
    float* red = w2 + MATF;         // [0..7] warp partials, [8] alpha

    const int tid = threadIdx.x;
    const int tx = (tid & 15) * 4;
    const int ty = (tid >> 4) * 4;
    const int bidx = blockIdx.x;
    const float4* Ain4 = reinterpret_cast<const float4*>(adj + (size_t)bidx * 4096);

    // Load adj -> xs; scores = threshold(adj,0.5) kept in 16 registers.
    float scf[16];
#pragma unroll
    for (int s = 0; s < 4; s++) {
        const int e4 = tid + s * NTH;
        const float4 v = Ain4[e4];
        const int i = e4 >> 4, j = (e4 & 15) * 4;
        float* xp = xs + i * LDM + j;
        xp[0] = v.x; xp[1] = v.y; xp[2] = v.z; xp[3] = v.w;
        scf[s * 4 + 0] = (v.x > 0.5f) ? v.x : 0.0f;
        scf[s * 4 + 1] = (v.y > 0.5f) ? v.y : 0.0f;
        scf[s * 4 + 2] = (v.z > 0.5f) ? v.z : 0.0f;
        scf[s * 4 + 3] = (v.w > 0.5f) ? v.w : 0.0f;
    }
    if (tid == 0) red[8] = 0.0f;
    __syncthreads();

    const float INV64  = 1.0f / 64.0f;
    const float SHRINK = 0.002f * 0.01f;

    // Invariant at loop top (iter >= 1): pA = m^15(x), pB = m^3(x), pC free.
    float* pA = w0;
    float* pB = w1;
    float* pC = w2;

#pragma unroll 1
    for (int it = 0; it < 50; it++) {
        const float alpha = red[8];
        const bool need_poly = (alpha != 0.0f);   // iter 0 only

        if (need_poly) {
            // m^63 = ((m^15)^2)^2 @ m^3 — destinations distinct from sources.
            mm64(pC, pA, pA, tx, ty);  __syncthreads();  // m^30 -> pC (m^15 dead)
            mm64(pA, pC, pC, tx, ty);  __syncthreads();  // m^60 -> pA
            mm64(pC, pA, pB, tx, ty);  __syncthreads();  // m^63 -> pC (m^30 dead)
        }

        // x update (reads pC^T) fused with build of m = I + x*x/64 into pA.
        const float a2s = 2.0f * alpha * INV64;
#pragma unroll
        for (int s = 0; s < 4; s++) {
            const int e4 = tid + s * NTH;
            const int i = e4 >> 4, j = (e4 & 15) * 4;
            float* xp = xs + i * LDM + j;
            float* mp = pA + i * LDM + j;
#pragma unroll
            for (int c = 0; c < 4; c++) {
                float x = xp[c];
                float g = -scf[s * 4 + c];
                if (need_poly)
                    g += (a2s * x) * pC[(j + c) * LDM + i];
                const float til = x - 0.01f * g;
                float nx = fabsf(til) - SHRINK;
                nx = fmaxf(nx, 0.0f);
                x = 1.0f - fmaxf(1.0f - nx, 0.0f);
                xp[c] = x;
                mp[c] = x * x * INV64 + ((i == j + c) ? 1.0f : 0.0f);
            }
        }
        __syncthreads();

        // trace chain: m (pA) -> m^2, m^3, m^6, m^12, m^15; keep m^15 & m^3.
        mm64(pB, pA, pA, tx, ty);  __syncthreads();  // m^2  -> pB (old m^3 dead)
        mm64(pC, pB, pA, tx, ty);  __syncthreads();  // m^3  -> pC (m^63 dead)
        mm64(pB, pC, pC, tx, ty);  __syncthreads();  // m^6  -> pB (m^2 dead)
        mm64(pA, pB, pB, tx, ty);  __syncthreads();  // m^12 -> pA (m dead)
        mm64(pB, pA, pC, tx, ty);  __syncthreads();  // m^15 -> pB (m^6 dead)

        // h = trace(m^30)/64 - 1 ; trace(m^30) = dot(m^15, m^15^T)
        float part = 0.0f;
#pragma unroll
        for (int s = 0; s < 16; s++) {
            const int e = tid + s * NTH;
            const int i = e >> 6, k = e & 63;
            part += pB[i * LDM + k] * pB[k * LDM + i];
        }
#pragma unroll
        for (int off = 16; off > 0; off >>= 1)
            part += __shfl_xor_sync(0xFFFFFFFFu, part, off);
        if ((tid & 31) == 0) red[tid >> 5] = part;
        __syncthreads();
        if (tid == 0) {
            float t = 0.0f;
#pragma unroll
            for (int w = 0; w < 8; w++) t += red[w];
            red[8] += 0.01f * (t * INV64 - 1.0f);
        }

        // rotate: m^15 in pB, m^3 in pC, pA free.
        float* tmp = pA;
        pA = pB;      // m^15
        pB = pC;      // m^3
        pC = tmp;     // free
        __syncthreads();
    }

    // output = threshold(x, 0.5)
    float4* Out4 = reinterpret_cast<float4*>(out + (size_t)bidx * 4096);
#pragma unroll
    for (int s = 0; s < 4; s++) {
        const int e4 = tid + s * NTH;
        const int i = e4 >> 4, j = (e4 & 15) * 4;
        const float* xp = xs + i * LDM + j;
        float4 v;
        v.x = (xp[0] > 0.5f) ? xp[0] : 0.0f;
        v.y = (xp[1] > 0.5f) ? xp[1] : 0.0f;
        v.z = (xp[2] > 0.5f) ? xp[2] : 0.0f;
        v.w = (xp[3] > 0.5f) ? xp[3] : 0.0f;
        Out4[e4] = v;
    }
}

extern "C" void kernel_launch(void* const* d_in, const int* in_sizes, int n_in,
                              void* d_out, int out_size)
{
    const float* adj = (const float*)d_in[0];
    float* out = (float*)d_out;

    const int batches = in_sizes[0] >> 12;
    const size_t smem = (size_t)(4 * MATF + 16) * sizeof(float);

    cudaFuncSetAttribute(ppb_kernel, cudaFuncAttributeMaxDynamicSharedMemorySize, (int)smem);
    ppb_kernel<<<batches, NTH, smem>>>(adj, out);
}

// round 9
// speedup vs baseline: 2.5146x; 1.0139x over previous
#include <cuda_runtime.h>

// PostProcessingBlock: 50 NOTEARS-style iterations, 512 independent 64x64
// matrices, one 256-thread CTA per matrix, 3 CTAs/SM.
// 8 matmuls/iter: poly m^63 = ((m^15)^2)^2 @ m^3 reuses the trace chain's
// m^15/m^3; trace(m^30) = dot(m^15, m^15^T). mm64: f32x2 FMA, 4x4 tile.
// This round: alpha in registers (one fewer barrier), unroll-8 mainloop,
// pointer-walked operand addressing.

#define LDM   68
#define MATF  (64 * LDM)
#define NTH   256

typedef unsigned long long u64;

__device__ __forceinline__ u64 rep2(float v) {
    u64 r;
    asm("mov.b64 %0, {%1, %1};" : "=l"(r) : "r"(__float_as_uint(v)));
    return r;
}
__device__ __forceinline__ void ffma2(u64& d, u64 a, u64 b) {
    asm("fma.rn.f32x2 %0, %1, %2, %0;" : "+l"(d) : "l"(a), "l"(b));
}

// C = A @ B, 64x64x64 fp32 in smem, 256 threads, 4x4 tile per thread.
// Caller guarantees C distinct from A and B (A == B allowed).
__device__ __forceinline__ void mm64(float* __restrict__ C,
                                     const float* __restrict__ A,
                                     const float* __restrict__ B,
                                     int tx, int ty)
{
    u64 acc[4][2];
#pragma unroll
    for (int r = 0; r < 4; r++) { acc[r][0] = 0ULL; acc[r][1] = 0ULL; }

    const float* a0p = A + (ty + 0) * LDM;
    const float* a1p = A + (ty + 1) * LDM;
    const float* a2p = A + (ty + 2) * LDM;
    const float* a3p = A + (ty + 3) * LDM;
    const float* bp  = B + tx;

#pragma unroll 8
    for (int k0 = 0; k0 < 64; k0 += 4) {
        float a0[4], a1[4], a2[4], a3[4];
        *reinterpret_cast<float4*>(a0) = *reinterpret_cast<const float4*>(a0p); a0p += 4;
        *reinterpret_cast<float4*>(a1) = *reinterpret_cast<const float4*>(a1p); a1p += 4;
        *reinterpret_cast<float4*>(a2) = *reinterpret_cast<const float4*>(a2p); a2p += 4;
        *reinterpret_cast<float4*>(a3) = *reinterpret_cast<const float4*>(a3p); a3p += 4;

#pragma unroll
        for (int ki = 0; ki < 4; ki++) {
            const ulonglong2 b = *reinterpret_cast<const ulonglong2*>(bp);
            bp += LDM;
            ffma2(acc[0][0], rep2(a0[ki]), b.x);
            ffma2(acc[0][1], rep2(a0[ki]), b.y);
            ffma2(acc[1][0], rep2(a1[ki]), b.x);
            ffma2(acc[1][1], rep2(a1[ki]), b.y);
            ffma2(acc[2][0], rep2(a2[ki]), b.x);
            ffma2(acc[2][1], rep2(a2[ki]), b.y);
            ffma2(acc[3][0], rep2(a3[ki]), b.x);
            ffma2(acc[3][1], rep2(a3[ki]), b.y);
        }
    }

#pragma unroll
    for (int r = 0; r < 4; r++)
        *reinterpret_cast<ulonglong2*>(C + (ty + r) * LDM + tx) =
            make_ulonglong2(acc[r][0], acc[r][1]);
}

__global__ __launch_bounds__(NTH, 3)
void ppb_kernel(const float* __restrict__ adj, float* __restrict__ out)
{
    extern __shared__ float sm[];
    float* xs = sm;                 // current x
    float* w0 = xs + MATF;          // rotating work buffers
    float* w1 = w0 + MATF;
    float* w2 = w1 + MATF;
    float* red = w2 + MATF;         // [0..7] warp partials

    const int tid = threadIdx.x;
    const int tx = (tid & 15) * 4;
    const int ty = (tid >> 4) * 4;
    const int bidx = blockIdx.x;
    const float4* Ain4 = reinterpret_cast<const float4*>(adj + (size_t)bidx * 4096);

    // Load adj -> xs; scores = threshold(adj,0.5) kept in 16 registers.
    float scf[16];
#pragma unroll
    for (int s = 0; s < 4; s++) {
        const int e4 = tid + s * NTH;
        const float4 v = Ain4[e4];
        const int i = e4 >> 4, j = (e4 & 15) * 4;
        float* xp = xs + i * LDM + j;
        xp[0] = v.x; xp[1] = v.y; xp[2] = v.z; xp[3] = v.w;
        scf[s * 4 + 0] = (v.x > 0.5f) ? v.x : 0.0f;
        scf[s * 4 + 1] = (v.y > 0.5f) ? v.y : 0.0f;
        scf[s * 4 + 2] = (v.z > 0.5f) ? v.z : 0.0f;
        scf[s * 4 + 3] = (v.w > 0.5f) ? v.w : 0.0f;
    }
    __syncthreads();

    const float INV64  = 1.0f / 64.0f;
    const float SHRINK = 0.002f * 0.01f;

    // alpha lives in a register, updated identically by every thread.
    float alpha = 0.0f;

    // Invariant at loop top (iter >= 1): pA = m^15(x), pB = m^3(x), pC free.
    float* pA = w0;
    float* pB = w1;
    float* pC = w2;

#pragma unroll 1
    for (int it = 0; it < 50; it++) {
        const bool need_poly = (alpha != 0.0f);   // iter 0 only

        if (need_poly) {
            // m^63 = ((m^15)^2)^2 @ m^3 — destinations distinct from sources.
            mm64(pC, pA, pA, tx, ty);  __syncthreads();  // m^30 -> pC (m^15 dead)
            mm64(pA, pC, pC, tx, ty);  __syncthreads();  // m^60 -> pA
            mm64(pC, pA, pB, tx, ty);  __syncthreads();  // m^63 -> pC (m^30 dead)
        }

        // x update (reads pC^T) fused with build of m = I + x*x/64 into pA.
        const float a2s = 2.0f * alpha * INV64;
#pragma unroll
        for (int s = 0; s < 4; s++) {
            const int e4 = tid + s * NTH;
            const int i = e4 >> 4, j = (e4 & 15) * 4;
            float* xp = xs + i * LDM + j;
            float* mp = pA + i * LDM + j;
#pragma unroll
            for (int c = 0; c < 4; c++) {
                float x = xp[c];
                float g = -scf[s * 4 + c];
                if (need_poly)
                    g += (a2s * x) * pC[(j + c) * LDM + i];
                const float til = x - 0.01f * g;
                float nx = fabsf(til) - SHRINK;
                nx = fmaxf(nx, 0.0f);
                x = 1.0f - fmaxf(1.0f - nx, 0.0f);
                xp[c] = x;
                mp[c] = x * x * INV64 + ((i == j + c) ? 1.0f : 0.0f);
            }
        }
        __syncthreads();

        // trace chain: m (pA) -> m^2, m^3, m^6, m^12, m^15; keep m^15 & m^3.
        mm64(pB, pA, pA, tx, ty);  __syncthreads();  // m^2  -> pB (old m^3 dead)
        mm64(pC, pB, pA, tx, ty);  __syncthreads();  // m^3  -> pC (m^63 dead)
        mm64(pB, pC, pC, tx, ty);  __syncthreads();  // m^6  -> pB (m^2 dead)
        mm64(pA, pB, pB, tx, ty);  __syncthreads();  // m^12 -> pA (m dead)
        mm64(pB, pA, pC, tx, ty);  __syncthreads();  // m^15 -> pB (m^6 dead)

        // h = trace(m^30)/64 - 1 ; trace(m^30) = dot(m^15, m^15^T)
        float part = 0.0f;
#pragma unroll
        for (int s = 0; s < 16; s++) {
            const int e = tid + s * NTH;
            const int i = e >> 6, k = e & 63;
            part += pB[i * LDM + k] * pB[k * LDM + i];
        }
#pragma unroll
        for (int off = 16; off > 0; off >>= 1)
            part += __shfl_xor_sync(0xFFFFFFFFu, part, off);
        if ((tid & 31) == 0) red[tid >> 5] = part;
        __syncthreads();

        // Every thread redundantly sums the 8 partials (identical order ->
        // identical alpha in all threads); no second barrier needed because
        // red is next written only after 8 matmuls' worth of barriers.
        float t = 0.0f;
#pragma unroll
        for (int w = 0; w < 8; w++) t += red[w];
        alpha += 0.01f * (t * INV64 - 1.0f);

        // rotate: m^15 in pB, m^3 in pC, pA free.
        float* tmp = pA;
        pA = pB;      // m^15
        pB = pC;      // m^3
        pC = tmp;     // free
    }

    // output = threshold(x, 0.5)
    float4* Out4 = reinterpret_cast<float4*>(out + (size_t)bidx * 4096);
#pragma unroll
    for (int s = 0; s < 4; s++) {
        const int e4 = tid + s * NTH;
        const int i = e4 >> 4, j = (e4 & 15) * 4;
        const float* xp = xs + i * LDM + j;
        float4 v;
        v.x = (xp[0] > 0.5f) ? xp[0] : 0.0f;
        v.y = (xp[1] > 0.5f) ? xp[1] : 0.0f;
        v.z = (xp[2] > 0.5f) ? xp[2] : 0.0f;
        v.w = (xp[3] > 0.5f) ? xp[3] : 0.0f;
        Out4[e4] = v;
    }
}

extern "C" void kernel_launch(void* const* d_in, const int* in_sizes, int n_in,
                              void* d_out, int out_size)
{
    const float* adj = (const float*)d_in[0];
    float* out = (float*)d_out;

    const int batches = in_sizes[0] >> 12;
    const size_t smem = (size_t)(4 * MATF + 8) * sizeof(float);

    cudaFuncSetAttribute(ppb_kernel, cudaFuncAttributeMaxDynamicSharedMemorySize, (int)smem);
    ppb_kernel<<<batches, NTH, smem>>>(adj, out);
}